// round 1
// baseline (speedup 1.0000x reference)
#include <cuda_runtime.h>

// ShortConvolution: depthwise causal conv K=4 + SiLU.
// x: (B=4, T=4096, D=2048) fp32 ; weight: (D=2048, K=4) fp32
// y[b,t,d] = silu( sum_{k=0..3} w[d,k] * x[b, t+k-3, d] )   (x[t<0] = 0)

#define B_ 4
#define T_ 4096
#define D_ 2048
#define DV_ (D_ / 4)        // 512 float4 lanes across channels
#define TPT_ 8              // time steps per thread
#define NCHUNK_ (T_ / TPT_) // 512

__global__ __launch_bounds__(256, 4)
void shortconv_silu_kernel(const float4* __restrict__ x,
                           const float4* __restrict__ w,
                           float4* __restrict__ out) {
    const int gid = blockIdx.x * blockDim.x + threadIdx.x;
    const int dv  = gid % DV_;              // float4 lane along channels
    const int row = gid / DV_;              // (b, t-chunk)
    const int t0  = (row % NCHUNK_) * TPT_;
    const int b   = row / NCHUNK_;

    // weight layout (D, K): float4 w[c] = the 4 taps of channel c.
    // This thread owns channels 4*dv .. 4*dv+3.
    const float4 wa = w[4 * dv + 0];  // taps for .x channel
    const float4 wb = w[4 * dv + 1];  // taps for .y channel
    const float4 wc = w[4 * dv + 2];  // taps for .z channel
    const float4 wd = w[4 * dv + 3];  // taps for .w channel

    const size_t base = (size_t)b * T_ * DV_ + dv;
    const float4* __restrict__ xp = x + base;
    float4* __restrict__ op = out + base;

    // Load TPT+3 time samples (halo of 3 on the left; zero for t<0).
    float4 xs[TPT_ + 3];
#pragma unroll
    for (int i = 0; i < TPT_ + 3; ++i) {
        const int t = t0 + i - 3;
        if (t >= 0) {
            xs[i] = __ldg(&xp[(size_t)t * DV_]);
        } else {
            xs[i] = make_float4(0.f, 0.f, 0.f, 0.f);
        }
    }

#pragma unroll
    for (int j = 0; j < TPT_; ++j) {
        float4 y;
        // y[t0+j] = sum_k w[k] * x[t0+j+k-3]  ->  xs[j+k], k=0..3
        y.x = fmaf(wa.x, xs[j].x, fmaf(wa.y, xs[j+1].x, fmaf(wa.z, xs[j+2].x, wa.w * xs[j+3].x)));
        y.y = fmaf(wb.x, xs[j].y, fmaf(wb.y, xs[j+1].y, fmaf(wb.z, xs[j+2].y, wb.w * xs[j+3].y)));
        y.z = fmaf(wc.x, xs[j].z, fmaf(wc.y, xs[j+1].z, fmaf(wc.z, xs[j+2].z, wc.w * xs[j+3].z)));
        y.w = fmaf(wd.x, xs[j].w, fmaf(wd.y, xs[j+1].w, fmaf(wd.z, xs[j+2].w, wd.w * xs[j+3].w)));

        // SiLU: v * sigmoid(v) = v / (1 + exp(-v))
        y.x = y.x * __frcp_rn(1.f + __expf(-y.x));
        y.y = y.y * __frcp_rn(1.f + __expf(-y.y));
        y.z = y.z * __frcp_rn(1.f + __expf(-y.z));
        y.w = y.w * __frcp_rn(1.f + __expf(-y.w));

        op[(size_t)(t0 + j) * DV_] = y;
    }
}

extern "C" void kernel_launch(void* const* d_in, const int* in_sizes, int n_in,
                              void* d_out, int out_size) {
    const float4* x = (const float4*)d_in[0];
    const float4* w = (const float4*)d_in[1];
    float4* out = (float4*)d_out;

    const int total_threads = B_ * NCHUNK_ * DV_;   // 4 * 512 * 512 = 1,048,576
    const int block = 256;
    const int grid = total_threads / block;          // 4096

    shortconv_silu_kernel<<<grid, block>>>(x, w, out);
}

// round 2
// speedup vs baseline: 1.1923x; 1.1923x over previous
#include <cuda_runtime.h>

// ShortConvolution: depthwise causal conv K=4 + SiLU.
// x: (B=4, T=4096, D=2048) fp32 ; weight: (D=2048, K=4) fp32
// y[b,t,d] = silu( sum_{k=0..3} w[d,k] * x[b, t+k-3, d] )   (x[t<0] = 0)
//
// R2: packed f32x2 math (fma.rn.f32x2 / mul.rn.f32x2, PTX-only on sm_103a)
//     + single-MUFU SiLU via tanh.approx.f32.

#define B_ 4
#define T_ 4096
#define D_ 2048
#define DV_ (D_ / 4)        // 512 float4 lanes across channels
#define TPT_ 8              // time steps per thread
#define NCHUNK_ (T_ / TPT_) // 512

typedef unsigned long long u64;

__device__ __forceinline__ u64 pack2(float lo, float hi) {
    u64 r;
    asm("mov.b64 %0, {%1, %2};" : "=l"(r) : "f"(lo), "f"(hi));
    return r;
}
__device__ __forceinline__ void unpack2(u64 v, float& lo, float& hi) {
    asm("mov.b64 {%0, %1}, %2;" : "=f"(lo), "=f"(hi) : "l"(v));
}
__device__ __forceinline__ u64 fma2(u64 a, u64 b, u64 c) {
    u64 d;
    asm("fma.rn.f32x2 %0, %1, %2, %3;" : "=l"(d) : "l"(a), "l"(b), "l"(c));
    return d;
}
__device__ __forceinline__ u64 mul2(u64 a, u64 b) {
    u64 d;
    asm("mul.rn.f32x2 %0, %1, %2;" : "=l"(d) : "l"(a), "l"(b));
    return d;
}
__device__ __forceinline__ float tanh_fast(float v) {
    float r;
    asm("tanh.approx.f32 %0, %1;" : "=f"(r) : "f"(v));
    return r;
}

__global__ __launch_bounds__(256, 4)
void shortconv_silu_kernel(const float4* __restrict__ x,
                           const float4* __restrict__ w,
                           float4* __restrict__ out) {
    const int gid = blockIdx.x * blockDim.x + threadIdx.x;
    const int dv  = gid % DV_;              // float4 lane along channels
    const int row = gid / DV_;              // (b, t-chunk)
    const int t0  = (row % NCHUNK_) * TPT_;
    const int b   = row / NCHUNK_;

    // weight layout (D, K): float4 w[c] = the 4 taps of channel c.
    // This thread owns channels 4*dv .. 4*dv+3.
    const float4 wa = __ldg(&w[4 * dv + 0]);  // taps for .x channel
    const float4 wb = __ldg(&w[4 * dv + 1]);  // taps for .y channel
    const float4 wc = __ldg(&w[4 * dv + 2]);  // taps for .z channel
    const float4 wd = __ldg(&w[4 * dv + 3]);  // taps for .w channel

    // Packed taps: lo = channels (.x,.y), hi = channels (.z,.w)
    const u64 wlo0 = pack2(wa.x, wb.x), wlo1 = pack2(wa.y, wb.y);
    const u64 wlo2 = pack2(wa.z, wb.z), wlo3 = pack2(wa.w, wb.w);
    const u64 whi0 = pack2(wc.x, wd.x), whi1 = pack2(wc.y, wd.y);
    const u64 whi2 = pack2(wc.z, wd.z), whi3 = pack2(wc.w, wd.w);

    const u64 HALF2 = pack2(0.5f, 0.5f);

    const size_t base = (size_t)b * T_ * DV_ + dv;
    const float4* __restrict__ xp = x + base;
    float4* __restrict__ op = out + base;

    // Load TPT+3 time samples (halo of 3 on the left; zero for t<0).
    u64 xlo[TPT_ + 3], xhi[TPT_ + 3];
#pragma unroll
    for (int i = 0; i < TPT_ + 3; ++i) {
        const int t = t0 + i - 3;
        float4 v = make_float4(0.f, 0.f, 0.f, 0.f);
        if (t >= 0) v = __ldg(&xp[(size_t)t * DV_]);
        xlo[i] = pack2(v.x, v.y);
        xhi[i] = pack2(v.z, v.w);
    }

#pragma unroll
    for (int j = 0; j < TPT_; ++j) {
        // y = w0*x[j] + w1*x[j+1] + w2*x[j+2] + w3*x[j+3]
        u64 alo = mul2(wlo3, xlo[j + 3]);
        alo = fma2(wlo2, xlo[j + 2], alo);
        alo = fma2(wlo1, xlo[j + 1], alo);
        alo = fma2(wlo0, xlo[j + 0], alo);

        u64 ahi = mul2(whi3, xhi[j + 3]);
        ahi = fma2(whi2, xhi[j + 2], ahi);
        ahi = fma2(whi1, xhi[j + 1], ahi);
        ahi = fma2(whi0, xhi[j + 0], ahi);

        // SiLU: y * (0.5*tanh(0.5*y) + 0.5)   (single MUFU per element)
        u64 hlo = mul2(alo, HALF2);
        u64 hhi = mul2(ahi, HALF2);
        float h0, h1, h2, h3;
        unpack2(hlo, h0, h1);
        unpack2(hhi, h2, h3);
        const u64 tlo = pack2(tanh_fast(h0), tanh_fast(h1));
        const u64 thi = pack2(tanh_fast(h2), tanh_fast(h3));
        const u64 slo = fma2(tlo, HALF2, HALF2);
        const u64 shi = fma2(thi, HALF2, HALF2);
        const u64 ylo = mul2(alo, slo);
        const u64 yhi = mul2(ahi, shi);

        float4 o;
        unpack2(ylo, o.x, o.y);
        unpack2(yhi, o.z, o.w);
        op[(size_t)(t0 + j) * DV_] = o;
    }
}

extern "C" void kernel_launch(void* const* d_in, const int* in_sizes, int n_in,
                              void* d_out, int out_size) {
    const float4* x = (const float4*)d_in[0];
    const float4* w = (const float4*)d_in[1];
    float4* out = (float4*)d_out;

    const int total_threads = B_ * NCHUNK_ * DV_;   // 4 * 512 * 512 = 1,048,576
    const int block = 256;
    const int grid = total_threads / block;          // 4096

    shortconv_silu_kernel<<<grid, block>>>(x, w, out);
}